// round 15
// baseline (speedup 1.0000x reference)
#include <cuda_runtime.h>

typedef unsigned long long u64;

#define THREADS 512
#define NATOM   128
#define KNB     127
#define NBATCH  64
#define BT      8

// ---- shared memory float offsets (e-strides == 8 mod 32 banks) ----
#define OFF_TY   0
#define OFF_W0   128      // [e*40 + o]
#define OFF_B0   288
#define OFF_W1   448      // [e*1608 + i*64 + pos] quarter tiles 16 @ 16qt (13,13,12,12)
#define E1STR    1608
#define OFF_B1   6880     // [e*72 + pos]
#define OFF_W2   7168     // [e*5608 + i*112 + pos] quarter = 25 contiguous @ 28qt (+3 pad)
#define E2STR    5608
#define OFF_B2   29600    // [e*136 + pos]
#define OFF_CS   30144    // [bb][3][128]   3*384
#define OFF_EA   31296    // [bb][k*4+c]    3*512 (float4 per k)
#define OFF_X    32832    // h1: [bb*6604 + slot*52 + i] / G: [slot*101 + m]
#define H1BUF    6604     // 127*52, 16B-aligned rows
#define H1STR    52
#define GSTR     101
#define OFF_UP   52644    // [kq*312 + c*104 + m]  (16B aligned)
#define OFF_US   53892    // 16B aligned
#define OFF_SIDX 54204
#define OFF_CNT  54332
#define OFF_ST   54336
#define SMEM_FLOATS 54344
#define SMEM_BYTES (SMEM_FLOATS * 4)

__device__ __forceinline__ float tanhx(float x) {
    float y; asm("tanh.approx.f32 %0, %1;" : "=f"(y) : "f"(x)); return y;
}
__device__ __forceinline__ u64 pack2(float lo, float hi) {
    u64 r; asm("mov.b64 %0, {%1, %2};" : "=l"(r) : "f"(lo), "f"(hi)); return r;
}
__device__ __forceinline__ float2 unpack2(u64 v) {
    float2 r; asm("mov.b64 {%0, %1}, %2;" : "=f"(r.x), "=f"(r.y) : "l"(v)); return r;
}
__device__ __forceinline__ u64 fma2(u64 a, u64 b, u64 c) {
    u64 r; asm("fma.rn.f32x2 %0, %1, %2, %3;" : "=l"(r) : "l"(a), "l"(b), "l"(c)); return r;
}
#define BARG(id) asm volatile("bar.sync %0, 128;" :: "r"(id) : "memory")

extern __shared__ float sm[];

template<int NB>
__device__ __forceinline__ void tile_body(
    const float* __restrict__ coords, float* __restrict__ out,
    int n, int tid, int qt, int slot, bool active, int j,
    const float* w0e, const float* b0e,
    const float* w1q, const float* b1q,
    const float* w2q, const float* b2q,
    int tbase1, int sz1, int barid, int b0i)
{
    __syncthreads();   // guard CS/EA/X reuse from previous tile
    for (int i = tid; i < NB * 384; i += THREADS) {
        int bb = i / 384, ii = i % 384;
        sm[OFF_CS + bb * 384 + (ii % 3) * 128 + ii / 3] =
            coords[(size_t)(b0i + bb) * 384 + ii];
    }
    __syncthreads();

    // ---- env: x[b] = 1/d, EA packed float4 (qt==0 writes) ----
    float x[NB];
    #pragma unroll
    for (int bb = 0; bb < NB; bb++) {
        const float* cs = sm + OFF_CS + bb * 384;
        float rx = cs[n]       - cs[j];
        float ry = cs[128 + n] - cs[128 + j];
        float rz = cs[256 + n] - cs[256 + j];
        float dinv = rsqrtf(rx * rx + ry * ry + rz * rz);
        float di2 = dinv * dinv;
        if (qt == 0 && active) {
            float4* ea4 = (float4*)(sm + OFF_EA + bb * 512);
            ea4[slot] = make_float4(rx * di2, ry * di2, rz * di2, 0.0f);
        }
        x[bb] = dinv;
    }

    // per-thread h1 row bases (16B-aligned, stride 52)
    const float* h1base[NB];
    #pragma unroll
    for (int bb = 0; bb < NB; bb++)
        h1base[bb] = sm + OFF_X + bb * H1BUF + slot * H1STR;

    // ---- layer1: quarter (13 real outs = 7 u64), h0 inline, NB batches ----
    {
        u64 acc[NB][7];
        {
            #pragma unroll
            for (int t = 0; t < 3; t++) {
                ulonglong2 bv = *(const ulonglong2*)(b1q + t * 4);
                #pragma unroll
                for (int bb = 0; bb < NB; bb++) { acc[bb][2*t] = bv.x; acc[bb][2*t+1] = bv.y; }
            }
            u64 bl = *(const u64*)(b1q + 12);
            #pragma unroll
            for (int bb = 0; bb < NB; bb++) acc[bb][6] = bl;
        }
        #pragma unroll 5
        for (int i = 0; i < 25; i++) {
            float w0 = w0e[i], bi0 = b0e[i];
            u64 hd[NB];
            #pragma unroll
            for (int bb = 0; bb < NB; bb++) {
                float h = tanhx(fmaf(x[bb], w0, bi0));
                hd[bb] = pack2(h, h);
            }
            const float* wp = w1q + i * 64;
            #pragma unroll
            for (int t = 0; t < 3; t++) {
                ulonglong2 w = *(const ulonglong2*)(wp + t * 4);
                #pragma unroll
                for (int bb = 0; bb < NB; bb++) {
                    acc[bb][2*t]   = fma2(w.x, hd[bb], acc[bb][2*t]);
                    acc[bb][2*t+1] = fma2(w.y, hd[bb], acc[bb][2*t+1]);
                }
            }
            u64 wl = *(const u64*)(wp + 12);
            #pragma unroll
            for (int bb = 0; bb < NB; bb++)
                acc[bb][6] = fma2(wl, hd[bb], acc[bb][6]);
        }
        if (active) {
            #pragma unroll
            for (int q = 0; q < 7; q++) {
                int l0 = 2 * q, l1 = 2 * q + 1;
                #pragma unroll
                for (int bb = 0; bb < NB; bb++) {
                    float2 v = unpack2(acc[bb][q]);
                    float* h1p = (float*)h1base[bb];
                    if (l0 < sz1) {
                        int o = tbase1 + l0, r = (o < 25) ? o : o - 25;
                        h1p[o] = tanhx(v.x) + tanhx(fmaf(x[bb], w0e[r], b0e[r]));
                    }
                    if (l1 < sz1) {
                        int o = tbase1 + l1, r = (o < 25) ? o : o - 25;
                        h1p[o] = tanhx(v.y) + tanhx(fmaf(x[bb], w0e[r], b0e[r]));
                    }
                }
            }
        }
    }
    BARG(barid);   // h1 complete within pair-group

    // ---- layer2: quarter 25 outs, two register sub-passes, float4 h1 ----
    float g[NB][25];
    const int roff = 25 * (qt & 1);
    // sub-pass A: outs l in [0,16)
    {
        u64 acc[NB][8];
        #pragma unroll
        for (int t = 0; t < 4; t++) {
            ulonglong2 bv = *(const ulonglong2*)(b2q + t * 4);
            #pragma unroll
            for (int bb = 0; bb < NB; bb++) { acc[bb][2*t] = bv.x; acc[bb][2*t+1] = bv.y; }
        }
        #pragma unroll 3
        for (int c = 0; c < 12; c++) {
            float hr[NB][4];
            #pragma unroll
            for (int bb = 0; bb < NB; bb++) {
                float4 hv = *(const float4*)(h1base[bb] + c * 4);
                hr[bb][0] = hv.x; hr[bb][1] = hv.y; hr[bb][2] = hv.z; hr[bb][3] = hv.w;
            }
            #pragma unroll
            for (int ii = 0; ii < 4; ii++) {
                const float* wp = w2q + (c * 4 + ii) * 112;
                u64 hd[NB];
                #pragma unroll
                for (int bb = 0; bb < NB; bb++) hd[bb] = pack2(hr[bb][ii], hr[bb][ii]);
                #pragma unroll
                for (int t = 0; t < 4; t++) {
                    ulonglong2 w = *(const ulonglong2*)(wp + t * 4);
                    #pragma unroll
                    for (int bb = 0; bb < NB; bb++) {
                        acc[bb][2*t]   = fma2(w.x, hd[bb], acc[bb][2*t]);
                        acc[bb][2*t+1] = fma2(w.y, hd[bb], acc[bb][2*t+1]);
                    }
                }
            }
        }
        {   // tail i = 48, 49
            float hr[NB][2];
            #pragma unroll
            for (int bb = 0; bb < NB; bb++) {
                float2 hv = *(const float2*)(h1base[bb] + 48);
                hr[bb][0] = hv.x; hr[bb][1] = hv.y;
            }
            #pragma unroll
            for (int ii = 0; ii < 2; ii++) {
                const float* wp = w2q + (48 + ii) * 112;
                u64 hd[NB];
                #pragma unroll
                for (int bb = 0; bb < NB; bb++) hd[bb] = pack2(hr[bb][ii], hr[bb][ii]);
                #pragma unroll
                for (int t = 0; t < 4; t++) {
                    ulonglong2 w = *(const ulonglong2*)(wp + t * 4);
                    #pragma unroll
                    for (int bb = 0; bb < NB; bb++) {
                        acc[bb][2*t]   = fma2(w.x, hd[bb], acc[bb][2*t]);
                        acc[bb][2*t+1] = fma2(w.y, hd[bb], acc[bb][2*t+1]);
                    }
                }
            }
        }
        #pragma unroll
        for (int q = 0; q < 8; q++) {
            int l0 = 2 * q, l1 = 2 * q + 1;
            #pragma unroll
            for (int bb = 0; bb < NB; bb++) {
                float2 v = unpack2(acc[bb][q]);
                g[bb][l0] = tanhx(v.x) + h1base[bb][roff + l0];
                g[bb][l1] = tanhx(v.y) + h1base[bb][roff + l1];
            }
        }
    }
    // sub-pass B: outs l in [16,25): 5 u64 (last slot's hi is pad)
    {
        u64 acc[NB][5];
        {
            #pragma unroll
            for (int t = 0; t < 2; t++) {
                ulonglong2 bv = *(const ulonglong2*)(b2q + 16 + t * 4);
                #pragma unroll
                for (int bb = 0; bb < NB; bb++) { acc[bb][2*t] = bv.x; acc[bb][2*t+1] = bv.y; }
            }
            u64 bl = *(const u64*)(b2q + 24);
            #pragma unroll
            for (int bb = 0; bb < NB; bb++) acc[bb][4] = bl;
        }
        #pragma unroll 3
        for (int c = 0; c < 12; c++) {
            float hr[NB][4];
            #pragma unroll
            for (int bb = 0; bb < NB; bb++) {
                float4 hv = *(const float4*)(h1base[bb] + c * 4);
                hr[bb][0] = hv.x; hr[bb][1] = hv.y; hr[bb][2] = hv.z; hr[bb][3] = hv.w;
            }
            #pragma unroll
            for (int ii = 0; ii < 4; ii++) {
                const float* wp = w2q + (c * 4 + ii) * 112 + 16;
                u64 hd[NB];
                #pragma unroll
                for (int bb = 0; bb < NB; bb++) hd[bb] = pack2(hr[bb][ii], hr[bb][ii]);
                #pragma unroll
                for (int t = 0; t < 2; t++) {
                    ulonglong2 w = *(const ulonglong2*)(wp + t * 4);
                    #pragma unroll
                    for (int bb = 0; bb < NB; bb++) {
                        acc[bb][2*t]   = fma2(w.x, hd[bb], acc[bb][2*t]);
                        acc[bb][2*t+1] = fma2(w.y, hd[bb], acc[bb][2*t+1]);
                    }
                }
                u64 wl = *(const u64*)(wp + 8);
                #pragma unroll
                for (int bb = 0; bb < NB; bb++)
                    acc[bb][4] = fma2(wl, hd[bb], acc[bb][4]);
            }
        }
        {   // tail i = 48, 49
            float hr[NB][2];
            #pragma unroll
            for (int bb = 0; bb < NB; bb++) {
                float2 hv = *(const float2*)(h1base[bb] + 48);
                hr[bb][0] = hv.x; hr[bb][1] = hv.y;
            }
            #pragma unroll
            for (int ii = 0; ii < 2; ii++) {
                const float* wp = w2q + (48 + ii) * 112 + 16;
                u64 hd[NB];
                #pragma unroll
                for (int bb = 0; bb < NB; bb++) hd[bb] = pack2(hr[bb][ii], hr[bb][ii]);
                #pragma unroll
                for (int t = 0; t < 2; t++) {
                    ulonglong2 w = *(const ulonglong2*)(wp + t * 4);
                    #pragma unroll
                    for (int bb = 0; bb < NB; bb++) {
                        acc[bb][2*t]   = fma2(w.x, hd[bb], acc[bb][2*t]);
                        acc[bb][2*t+1] = fma2(w.y, hd[bb], acc[bb][2*t+1]);
                    }
                }
                u64 wl = *(const u64*)(wp + 8);
                #pragma unroll
                for (int bb = 0; bb < NB; bb++)
                    acc[bb][4] = fma2(wl, hd[bb], acc[bb][4]);
            }
        }
        #pragma unroll
        for (int q = 0; q < 5; q++) {
            int l0 = 16 + 2 * q, l1 = l0 + 1;
            #pragma unroll
            for (int bb = 0; bb < NB; bb++) {
                float2 v = unpack2(acc[bb][q]);
                if (l0 < 25) g[bb][l0] = tanhx(v.x) + h1base[bb][roff + l0];
                if (l1 < 25) g[bb][l1] = tanhx(v.y) + h1base[bb][roff + l1];
            }
        }
    }
    __syncthreads();   // all h1 reads done; X becomes G

    #pragma unroll
    for (int bb = 0; bb < NB; bb++) {
        if (active) {
            float* grow = sm + OFF_X + slot * GSTR + 25 * qt;
            #pragma unroll
            for (int l = 0; l < 25; l++) grow[l] = g[bb][l];
        }
        __syncthreads();

        // U[c][m] = sum_k ea4[k]*G[k][m]; 4 k-chunks of 32
        const int m  = tid & 127;
        const int kq = tid >> 7;
        float u0 = 0.0f, u1 = 0.0f, u2 = 0.0f;
        if (m < 100) {
            const int kb = kq * 32;
            const int ke = (kq == 3) ? KNB : kb + 32;
            const float* gp = sm + OFF_X + m;
            const float4* ep4 = (const float4*)(sm + OFF_EA + bb * 512);
            #pragma unroll 4
            for (int kk = kb; kk < ke; kk++) {
                float4 ea = ep4[kk];
                float gv = gp[kk * GSTR];
                u0 = fmaf(ea.x, gv, u0);
                u1 = fmaf(ea.y, gv, u1);
                u2 = fmaf(ea.z, gv, u2);
            }
            sm[OFF_UP + kq * 312 + m]       = u0;
            sm[OFF_UP + kq * 312 + 104 + m] = u1;
            sm[OFF_UP + kq * 312 + 208 + m] = u2;
        }
        __syncthreads();
        float us0 = 0.0f, us1 = 0.0f, us2 = 0.0f;
        if (tid < 100) {
            #pragma unroll
            for (int qq = 0; qq < 4; qq++) {
                us0 += sm[OFF_UP + qq * 312 + tid];
                us1 += sm[OFF_UP + qq * 312 + 104 + tid];
                us2 += sm[OFF_UP + qq * 312 + 208 + tid];
            }
            sm[OFF_US + tid]       = us0;
            sm[OFF_US + 104 + tid] = us1;
            sm[OFF_US + 208 + tid] = us2;
        }
        __syncthreads();
        if (tid < 100) {
            float4 a0 = *(const float4*)(sm + OFF_US);
            float4 a1 = *(const float4*)(sm + OFF_US + 104);
            float4 a2 = *(const float4*)(sm + OFF_US + 208);
            float4 r;
            r.x = us0 * a0.x + us1 * a1.x + us2 * a2.x;
            r.y = us0 * a0.y + us1 * a1.y + us2 * a2.y;
            r.z = us0 * a0.z + us1 * a1.z + us2 * a2.z;
            r.w = us0 * a0.w + us1 * a1.w + us2 * a2.w;
            *(float4*)(out + ((size_t)(b0i + bb) * NATOM + n) * 400 + tid * 4) = r;
        }
        __syncthreads();   // G reads done before next batch's stores
    }
}

__global__ void __launch_bounds__(THREADS, 1)
feat_kernel(const float* __restrict__ coords, const int* __restrict__ types,
            const float* __restrict__ W0g, const float* __restrict__ B0g,
            const float* __restrict__ W1g, const float* __restrict__ B1g,
            const float* __restrict__ W2g, const float* __restrict__ B2g,
            float* __restrict__ out)
{
    const int n    = blockIdx.x;
    const int tid  = threadIdx.x;
    const int warp = tid >> 5;
    const int lane = tid & 31;
    const int pw   = warp & 3;
    const int qt   = warp >> 2;
    int* smi = (int*)sm;

    const int eb = types[n] * 4;

    for (int i = OFF_W0 + tid; i < OFF_CS; i += THREADS) sm[i] = 0.0f;
    if (tid < 128) smi[OFF_TY + tid] = types[tid];
    __syncthreads();

    for (int i = tid; i < 100; i += THREADS) {
        int o = i % 25, e = i / 25;
        sm[OFF_W0 + e * 40 + o] = W0g[(eb + e) * 25 + o];
        sm[OFF_B0 + e * 40 + o] = B0g[(eb + e) * 25 + o];
    }
    for (int idx = tid; idx < 4 * 50 * 25; idx += THREADS) {
        int i = idx % 25, o = (idx / 25) % 50, e = idx / 1250;
        int pos = (o < 13) ? o : (o < 26) ? o + 3 : (o < 38) ? o + 6 : o + 10;
        sm[OFF_W1 + e * E1STR + i * 64 + pos] = W1g[(eb + e) * 1250 + o * 25 + i];
    }
    for (int idx = tid; idx < 200; idx += THREADS) {
        int o = idx % 50, e = idx / 50;
        int pos = (o < 13) ? o : (o < 26) ? o + 3 : (o < 38) ? o + 6 : o + 10;
        sm[OFF_B1 + e * 72 + pos] = B1g[(eb + e) * 50 + o];
    }
    for (int idx = tid; idx < 4 * 100 * 50; idx += THREADS) {
        int i = idx % 50, m = (idx / 50) % 100, e = idx / 5000;
        int pos = m + 3 * (m / 25);
        sm[OFF_W2 + e * E2STR + i * 112 + pos] = W2g[(eb + e) * 5000 + m * 50 + i];
    }
    for (int idx = tid; idx < 400; idx += THREADS) {
        int m = idx % 100, e = idx / 100;
        int pos = m + 3 * (m / 25);
        sm[OFF_B2 + e * 136 + pos] = B2g[(eb + e) * 100 + m];
    }

    if (tid < 4) {
        int c = 0;
        for (int j2 = 0; j2 < 128; j2++)
            if (j2 != n && smi[OFF_TY + j2] == tid) c++;
        smi[OFF_CNT + tid] = c;
    }
    __syncthreads();
    if (tid == 0) {
        int s = 0;
        #pragma unroll
        for (int e = 0; e < 4; e++) { smi[OFF_ST + e] = s; s += smi[OFF_CNT + e]; }
        smi[OFF_ST + 4] = s;
    }
    __syncthreads();
    if (tid < 128 && tid != n) {
        int t = smi[OFF_TY + tid];
        int r = 0;
        for (int j2 = 0; j2 < tid; j2++)
            if (j2 != n && smi[OFF_TY + j2] == t) r++;
        smi[OFF_SIDX + smi[OFF_ST + t] + r] = tid;
    }
    __syncthreads();

    const int  slot   = (pw << 5) + lane;
    const bool active = slot < KNB;
    const int  j = active ? smi[OFF_SIDX + slot] : n;
    const int  e = active ? smi[OFF_TY + j] : 0;

    const float* w0e = sm + OFF_W0 + e * 40;
    const float* b0e = sm + OFF_B0 + e * 40;
    const float* w1q = sm + OFF_W1 + e * E1STR + 16 * qt;
    const float* b1q = sm + OFF_B1 + e * 72 + 16 * qt;
    const float* w2q = sm + OFF_W2 + e * E2STR + 28 * qt;
    const float* b2q = sm + OFF_B2 + e * 136 + 28 * qt;
    const int sz1    = (qt < 2) ? 13 : 12;
    const int tbase1 = (qt < 2) ? 13 * qt : 12 * qt + 2;
    const int barid  = 1 + pw;
    const int bbase  = blockIdx.y * BT;

    tile_body<3>(coords, out, n, tid, qt, slot, active, j,
                 w0e, b0e, w1q, b1q, w2q, b2q, tbase1, sz1, barid, bbase);
    tile_body<3>(coords, out, n, tid, qt, slot, active, j,
                 w0e, b0e, w1q, b1q, w2q, b2q, tbase1, sz1, barid, bbase + 3);
    tile_body<2>(coords, out, n, tid, qt, slot, active, j,
                 w0e, b0e, w1q, b1q, w2q, b2q, tbase1, sz1, barid, bbase + 6);
}

extern "C" void kernel_launch(void* const* d_in, const int* in_sizes, int n_in,
                              void* d_out, int out_size)
{
    (void)in_sizes; (void)n_in; (void)out_size;
    const float* coords = (const float*)d_in[0];
    const int*   types  = (const int*)d_in[1];
    const float* W0g = (const float*)d_in[2];
    const float* B0g = (const float*)d_in[3];
    const float* W1g = (const float*)d_in[4];
    const float* B1g = (const float*)d_in[5];
    const float* W2g = (const float*)d_in[6];
    const float* B2g = (const float*)d_in[7];
    float* out = (float*)d_out;

    cudaFuncSetAttribute(feat_kernel, cudaFuncAttributeMaxDynamicSharedMemorySize, SMEM_BYTES);

    dim3 grid(NATOM, NBATCH / BT);   // (128, 8)
    feat_kernel<<<grid, THREADS, SMEM_BYTES>>>(coords, types,
                                               W0g, B0g, W1g, B1g, W2g, B2g, out);
}

// round 16
// speedup vs baseline: 1.0751x; 1.0751x over previous
#include <cuda_runtime.h>

typedef unsigned long long u64;

#define THREADS 512
#define NATOM   128
#define KNB     127
#define NBATCH  64
#define BT      8

// ---- shared memory float offsets (e-strides == 8 mod 32 banks) ----
#define OFF_TY   0
#define OFF_W0   128      // [e*40 + o]
#define OFF_B0   288
#define OFF_W1   448      // [e*1608 + i*64 + pos] quarter tiles 16 @ 16qt (13,13,12,12)
#define E1STR    1608
#define OFF_B1   6880     // [e*72 + pos]
#define OFF_W2   7168     // [e*5608 + i*112 + pos] quarter = 25 contiguous @ 28qt (+3 pad)
#define E2STR    5608
#define OFF_B2   29600    // [e*136 + pos]
#define OFF_CS   30144    // [bb][3][128]   3*384
#define OFF_EA   31296    // [bb][k*4+c]    3*512 (float4 per k)
#define OFF_X    32832    // h1: [bb*6477 + slot*51 + i] / G: [slot*101 + m]
#define H1BUF    6477
#define GSTR     101
#define OFF_UP   52264    // [kq*312 + c*104 + m]  (16B aligned)
#define OFF_US   53512    // 16B aligned
#define OFF_SIDX 53824
#define OFF_CNT  53952
#define OFF_ST   53956
#define SMEM_FLOATS 53964
#define SMEM_BYTES (SMEM_FLOATS * 4)

__device__ __forceinline__ float tanhx(float x) {
    float y; asm("tanh.approx.f32 %0, %1;" : "=f"(y) : "f"(x)); return y;
}
__device__ __forceinline__ u64 pack2(float lo, float hi) {
    u64 r; asm("mov.b64 %0, {%1, %2};" : "=l"(r) : "f"(lo), "f"(hi)); return r;
}
__device__ __forceinline__ float2 unpack2(u64 v) {
    float2 r; asm("mov.b64 {%0, %1}, %2;" : "=f"(r.x), "=f"(r.y) : "l"(v)); return r;
}
__device__ __forceinline__ u64 fma2(u64 a, u64 b, u64 c) {
    u64 r; asm("fma.rn.f32x2 %0, %1, %2, %3;" : "=l"(r) : "l"(a), "l"(b), "l"(c)); return r;
}
#define BARG(id) asm volatile("bar.sync %0, 128;" :: "r"(id) : "memory")

extern __shared__ float sm[];

template<int NB>
__device__ __forceinline__ void tile_body(
    const float* __restrict__ coords, float* __restrict__ out,
    int n, int tid, int qt, int slot, bool active, int j,
    const float* w0e, const float* b0e,
    const float* w1q, const float* b1q,
    const float* w2q, const float* b2q,
    int tbase1, int sz1, int barid, int b0i)
{
    __syncthreads();   // guard CS/EA/X reuse from previous tile
    for (int i = tid; i < NB * 384; i += THREADS) {
        int bb = i / 384, ii = i % 384;
        sm[OFF_CS + bb * 384 + (ii % 3) * 128 + ii / 3] =
            coords[(size_t)(b0i + bb) * 384 + ii];
    }
    __syncthreads();

    // ---- env: x[b] = 1/d, EA packed float4 (qt==0 writes) ----
    float x[NB];
    #pragma unroll
    for (int bb = 0; bb < NB; bb++) {
        const float* cs = sm + OFF_CS + bb * 384;
        float rx = cs[n]       - cs[j];
        float ry = cs[128 + n] - cs[128 + j];
        float rz = cs[256 + n] - cs[256 + j];
        float dinv = rsqrtf(rx * rx + ry * ry + rz * rz);
        float di2 = dinv * dinv;
        if (qt == 0 && active) {
            float4* ea4 = (float4*)(sm + OFF_EA + bb * 512);
            ea4[slot] = make_float4(rx * di2, ry * di2, rz * di2, 0.0f);
        }
        x[bb] = dinv;
    }

    // per-thread h1 row bases (hoisted once)
    const float* h1base[NB];
    #pragma unroll
    for (int bb = 0; bb < NB; bb++)
        h1base[bb] = sm + OFF_X + bb * H1BUF + slot * 51;

    // ---- layer1: quarter (13 real outs = 7 u64), h0 inline, NB batches ----
    {
        u64 acc[NB][7];
        {
            #pragma unroll
            for (int t = 0; t < 3; t++) {
                ulonglong2 bv = *(const ulonglong2*)(b1q + t * 4);
                #pragma unroll
                for (int bb = 0; bb < NB; bb++) { acc[bb][2*t] = bv.x; acc[bb][2*t+1] = bv.y; }
            }
            u64 bl = *(const u64*)(b1q + 12);
            #pragma unroll
            for (int bb = 0; bb < NB; bb++) acc[bb][6] = bl;
        }
        #pragma unroll
        for (int i = 0; i < 25; i++) {
            float w0 = w0e[i], bi0 = b0e[i];
            u64 hd[NB];
            #pragma unroll
            for (int bb = 0; bb < NB; bb++) {
                float h = tanhx(fmaf(x[bb], w0, bi0));
                hd[bb] = pack2(h, h);
            }
            const float* wp = w1q + i * 64;
            #pragma unroll
            for (int t = 0; t < 3; t++) {
                ulonglong2 w = *(const ulonglong2*)(wp + t * 4);
                #pragma unroll
                for (int bb = 0; bb < NB; bb++) {
                    acc[bb][2*t]   = fma2(w.x, hd[bb], acc[bb][2*t]);
                    acc[bb][2*t+1] = fma2(w.y, hd[bb], acc[bb][2*t+1]);
                }
            }
            u64 wl = *(const u64*)(wp + 12);
            #pragma unroll
            for (int bb = 0; bb < NB; bb++)
                acc[bb][6] = fma2(wl, hd[bb], acc[bb][6]);
        }
        if (active) {
            #pragma unroll
            for (int q = 0; q < 7; q++) {
                int l0 = 2 * q, l1 = 2 * q + 1;
                #pragma unroll
                for (int bb = 0; bb < NB; bb++) {
                    float2 v = unpack2(acc[bb][q]);
                    float* h1p = (float*)h1base[bb];
                    if (l0 < sz1) {
                        int o = tbase1 + l0, r = (o < 25) ? o : o - 25;
                        h1p[o] = tanhx(v.x) + tanhx(fmaf(x[bb], w0e[r], b0e[r]));
                    }
                    if (l1 < sz1) {
                        int o = tbase1 + l1, r = (o < 25) ? o : o - 25;
                        h1p[o] = tanhx(v.y) + tanhx(fmaf(x[bb], w0e[r], b0e[r]));
                    }
                }
            }
        }
    }
    BARG(barid);   // h1 complete within pair-group

    // ---- layer2: quarter 25 outs, two register sub-passes ----
    float g[NB][25];
    const int roff = 25 * (qt & 1);
    // sub-pass A: outs l in [0,16)
    {
        u64 acc[NB][8];
        #pragma unroll
        for (int t = 0; t < 4; t++) {
            ulonglong2 bv = *(const ulonglong2*)(b2q + t * 4);
            #pragma unroll
            for (int bb = 0; bb < NB; bb++) { acc[bb][2*t] = bv.x; acc[bb][2*t+1] = bv.y; }
        }
        #pragma unroll 2
        for (int c = 0; c < 10; c++) {
            float hr[NB][5];
            #pragma unroll
            for (int ii = 0; ii < 5; ii++)
                #pragma unroll
                for (int bb = 0; bb < NB; bb++)
                    hr[bb][ii] = h1base[bb][c * 5 + ii];
            #pragma unroll
            for (int ii = 0; ii < 5; ii++) {
                const float* wp = w2q + (c * 5 + ii) * 112;
                u64 hd[NB];
                #pragma unroll
                for (int bb = 0; bb < NB; bb++) hd[bb] = pack2(hr[bb][ii], hr[bb][ii]);
                #pragma unroll
                for (int t = 0; t < 4; t++) {
                    ulonglong2 w = *(const ulonglong2*)(wp + t * 4);
                    #pragma unroll
                    for (int bb = 0; bb < NB; bb++) {
                        acc[bb][2*t]   = fma2(w.x, hd[bb], acc[bb][2*t]);
                        acc[bb][2*t+1] = fma2(w.y, hd[bb], acc[bb][2*t+1]);
                    }
                }
            }
        }
        #pragma unroll
        for (int q = 0; q < 8; q++) {
            int l0 = 2 * q, l1 = 2 * q + 1;
            #pragma unroll
            for (int bb = 0; bb < NB; bb++) {
                float2 v = unpack2(acc[bb][q]);
                g[bb][l0] = tanhx(v.x) + h1base[bb][roff + l0];
                g[bb][l1] = tanhx(v.y) + h1base[bb][roff + l1];
            }
        }
    }
    // sub-pass B: outs l in [16,25): 5 u64 (last slot's hi is pad)
    {
        u64 acc[NB][5];
        {
            #pragma unroll
            for (int t = 0; t < 2; t++) {
                ulonglong2 bv = *(const ulonglong2*)(b2q + 16 + t * 4);
                #pragma unroll
                for (int bb = 0; bb < NB; bb++) { acc[bb][2*t] = bv.x; acc[bb][2*t+1] = bv.y; }
            }
            u64 bl = *(const u64*)(b2q + 24);
            #pragma unroll
            for (int bb = 0; bb < NB; bb++) acc[bb][4] = bl;
        }
        #pragma unroll 2
        for (int c = 0; c < 10; c++) {
            float hr[NB][5];
            #pragma unroll
            for (int ii = 0; ii < 5; ii++)
                #pragma unroll
                for (int bb = 0; bb < NB; bb++)
                    hr[bb][ii] = h1base[bb][c * 5 + ii];
            #pragma unroll
            for (int ii = 0; ii < 5; ii++) {
                const float* wp = w2q + (c * 5 + ii) * 112 + 16;
                u64 hd[NB];
                #pragma unroll
                for (int bb = 0; bb < NB; bb++) hd[bb] = pack2(hr[bb][ii], hr[bb][ii]);
                #pragma unroll
                for (int t = 0; t < 2; t++) {
                    ulonglong2 w = *(const ulonglong2*)(wp + t * 4);
                    #pragma unroll
                    for (int bb = 0; bb < NB; bb++) {
                        acc[bb][2*t]   = fma2(w.x, hd[bb], acc[bb][2*t]);
                        acc[bb][2*t+1] = fma2(w.y, hd[bb], acc[bb][2*t+1]);
                    }
                }
                u64 wl = *(const u64*)(wp + 8);
                #pragma unroll
                for (int bb = 0; bb < NB; bb++)
                    acc[bb][4] = fma2(wl, hd[bb], acc[bb][4]);
            }
        }
        #pragma unroll
        for (int q = 0; q < 5; q++) {
            int l0 = 16 + 2 * q, l1 = l0 + 1;
            #pragma unroll
            for (int bb = 0; bb < NB; bb++) {
                float2 v = unpack2(acc[bb][q]);
                if (l0 < 25) g[bb][l0] = tanhx(v.x) + h1base[bb][roff + l0];
                if (l1 < 25) g[bb][l1] = tanhx(v.y) + h1base[bb][roff + l1];
            }
        }
    }
    __syncthreads();   // all h1 reads done; X becomes G

    #pragma unroll
    for (int bb = 0; bb < NB; bb++) {
        if (active) {
            float* grow = sm + OFF_X + slot * GSTR + 25 * qt;
            #pragma unroll
            for (int l = 0; l < 25; l++) grow[l] = g[bb][l];
        }
        __syncthreads();

        // U[c][m] = sum_k ea4[k]*G[k][m]; 4 k-chunks of 32
        const int m  = tid & 127;
        const int kq = tid >> 7;
        float u0 = 0.0f, u1 = 0.0f, u2 = 0.0f;
        if (m < 100) {
            const int kb = kq * 32;
            const int ke = (kq == 3) ? KNB : kb + 32;
            const float* gp = sm + OFF_X + m;
            const float4* ep4 = (const float4*)(sm + OFF_EA + bb * 512);
            #pragma unroll 4
            for (int kk = kb; kk < ke; kk++) {
                float4 ea = ep4[kk];
                float gv = gp[kk * GSTR];
                u0 = fmaf(ea.x, gv, u0);
                u1 = fmaf(ea.y, gv, u1);
                u2 = fmaf(ea.z, gv, u2);
            }
            sm[OFF_UP + kq * 312 + m]       = u0;
            sm[OFF_UP + kq * 312 + 104 + m] = u1;
            sm[OFF_UP + kq * 312 + 208 + m] = u2;
        }
        __syncthreads();
        float us0 = 0.0f, us1 = 0.0f, us2 = 0.0f;
        if (tid < 100) {
            #pragma unroll
            for (int qq = 0; qq < 4; qq++) {
                us0 += sm[OFF_UP + qq * 312 + tid];
                us1 += sm[OFF_UP + qq * 312 + 104 + tid];
                us2 += sm[OFF_UP + qq * 312 + 208 + tid];
            }
            sm[OFF_US + tid]       = us0;
            sm[OFF_US + 104 + tid] = us1;
            sm[OFF_US + 208 + tid] = us2;
        }
        __syncthreads();
        if (tid < 100) {
            // vectorized: U[c][0..3] as 3 broadcast LDS.128
            float4 a0 = *(const float4*)(sm + OFF_US);
            float4 a1 = *(const float4*)(sm + OFF_US + 104);
            float4 a2 = *(const float4*)(sm + OFF_US + 208);
            float4 r;
            r.x = us0 * a0.x + us1 * a1.x + us2 * a2.x;
            r.y = us0 * a0.y + us1 * a1.y + us2 * a2.y;
            r.z = us0 * a0.z + us1 * a1.z + us2 * a2.z;
            r.w = us0 * a0.w + us1 * a1.w + us2 * a2.w;
            *(float4*)(out + ((size_t)(b0i + bb) * NATOM + n) * 400 + tid * 4) = r;
        }
        __syncthreads();   // G reads done before next batch's stores
    }
}

__global__ void __launch_bounds__(THREADS, 1)
feat_kernel(const float* __restrict__ coords, const int* __restrict__ types,
            const float* __restrict__ W0g, const float* __restrict__ B0g,
            const float* __restrict__ W1g, const float* __restrict__ B1g,
            const float* __restrict__ W2g, const float* __restrict__ B2g,
            float* __restrict__ out)
{
    const int n    = blockIdx.x;
    const int tid  = threadIdx.x;
    const int warp = tid >> 5;
    const int lane = tid & 31;
    const int pw   = warp & 3;
    const int qt   = warp >> 2;
    int* smi = (int*)sm;

    const int eb = types[n] * 4;

    for (int i = OFF_W0 + tid; i < OFF_CS; i += THREADS) sm[i] = 0.0f;
    if (tid < 128) smi[OFF_TY + tid] = types[tid];
    __syncthreads();

    for (int i = tid; i < 100; i += THREADS) {
        int o = i % 25, e = i / 25;
        sm[OFF_W0 + e * 40 + o] = W0g[(eb + e) * 25 + o];
        sm[OFF_B0 + e * 40 + o] = B0g[(eb + e) * 25 + o];
    }
    for (int idx = tid; idx < 4 * 50 * 25; idx += THREADS) {
        int i = idx % 25, o = (idx / 25) % 50, e = idx / 1250;
        int pos = (o < 13) ? o : (o < 26) ? o + 3 : (o < 38) ? o + 6 : o + 10;
        sm[OFF_W1 + e * E1STR + i * 64 + pos] = W1g[(eb + e) * 1250 + o * 25 + i];
    }
    for (int idx = tid; idx < 200; idx += THREADS) {
        int o = idx % 50, e = idx / 50;
        int pos = (o < 13) ? o : (o < 26) ? o + 3 : (o < 38) ? o + 6 : o + 10;
        sm[OFF_B1 + e * 72 + pos] = B1g[(eb + e) * 50 + o];
    }
    for (int idx = tid; idx < 4 * 100 * 50; idx += THREADS) {
        int i = idx % 50, m = (idx / 50) % 100, e = idx / 5000;
        int pos = m + 3 * (m / 25);
        sm[OFF_W2 + e * E2STR + i * 112 + pos] = W2g[(eb + e) * 5000 + m * 50 + i];
    }
    for (int idx = tid; idx < 400; idx += THREADS) {
        int m = idx % 100, e = idx / 100;
        int pos = m + 3 * (m / 25);
        sm[OFF_B2 + e * 136 + pos] = B2g[(eb + e) * 100 + m];
    }

    if (tid < 4) {
        int c = 0;
        for (int j2 = 0; j2 < 128; j2++)
            if (j2 != n && smi[OFF_TY + j2] == tid) c++;
        smi[OFF_CNT + tid] = c;
    }
    __syncthreads();
    if (tid == 0) {
        int s = 0;
        #pragma unroll
        for (int e = 0; e < 4; e++) { smi[OFF_ST + e] = s; s += smi[OFF_CNT + e]; }
        smi[OFF_ST + 4] = s;
    }
    __syncthreads();
    if (tid < 128 && tid != n) {
        int t = smi[OFF_TY + tid];
        int r = 0;
        for (int j2 = 0; j2 < tid; j2++)
            if (j2 != n && smi[OFF_TY + j2] == t) r++;
        smi[OFF_SIDX + smi[OFF_ST + t] + r] = tid;
    }
    __syncthreads();

    const int  slot   = (pw << 5) + lane;
    const bool active = slot < KNB;
    const int  j = active ? smi[OFF_SIDX + slot] : n;
    const int  e = active ? smi[OFF_TY + j] : 0;

    const float* w0e = sm + OFF_W0 + e * 40;
    const float* b0e = sm + OFF_B0 + e * 40;
    const float* w1q = sm + OFF_W1 + e * E1STR + 16 * qt;
    const float* b1q = sm + OFF_B1 + e * 72 + 16 * qt;
    const float* w2q = sm + OFF_W2 + e * E2STR + 28 * qt;
    const float* b2q = sm + OFF_B2 + e * 136 + 28 * qt;
    const int sz1    = (qt < 2) ? 13 : 12;
    const int tbase1 = (qt < 2) ? 13 * qt : 12 * qt + 2;
    const int barid  = 1 + pw;
    const int bbase  = blockIdx.y * BT;

    tile_body<3>(coords, out, n, tid, qt, slot, active, j,
                 w0e, b0e, w1q, b1q, w2q, b2q, tbase1, sz1, barid, bbase);
    tile_body<3>(coords, out, n, tid, qt, slot, active, j,
                 w0e, b0e, w1q, b1q, w2q, b2q, tbase1, sz1, barid, bbase + 3);
    tile_body<2>(coords, out, n, tid, qt, slot, active, j,
                 w0e, b0e, w1q, b1q, w2q, b2q, tbase1, sz1, barid, bbase + 6);
}

extern "C" void kernel_launch(void* const* d_in, const int* in_sizes, int n_in,
                              void* d_out, int out_size)
{
    (void)in_sizes; (void)n_in; (void)out_size;
    const float* coords = (const float*)d_in[0];
    const int*   types  = (const int*)d_in[1];
    const float* W0g = (const float*)d_in[2];
    const float* B0g = (const float*)d_in[3];
    const float* W1g = (const float*)d_in[4];
    const float* B1g = (const float*)d_in[5];
    const float* W2g = (const float*)d_in[6];
    const float* B2g = (const float*)d_in[7];
    float* out = (float*)d_out;

    cudaFuncSetAttribute(feat_kernel, cudaFuncAttributeMaxDynamicSharedMemorySize, SMEM_BYTES);

    dim3 grid(NATOM, NBATCH / BT);   // (128, 8)
    feat_kernel<<<grid, THREADS, SMEM_BYTES>>>(coords, types,
                                               W0g, B0g, W1g, B1g, W2g, B2g, out);
}

// round 17
// speedup vs baseline: 1.0795x; 1.0041x over previous
#include <cuda_runtime.h>

typedef unsigned long long u64;

#define THREADS 512
#define NATOM   128
#define KNB     127
#define NBATCH  64
#define BT      8

// ---- shared memory float offsets (e-strides == 8 mod 32 banks) ----
#define OFF_TY   0
#define OFF_W0   128      // [e*40 + o]
#define OFF_B0   288
#define OFF_W1   448      // [e*1608 + i*64 + pos] quarter tiles 16 @ 16qt (13,13,12,12)
#define E1STR    1608
#define OFF_B1   6880     // [e*72 + pos]
#define OFF_W2   7168     // [e*5608 + i*112 + pos] quarter = 25 contiguous @ 28qt (+3 pad)
#define E2STR    5608
#define OFF_B2   29600    // [e*136 + pos]
#define OFF_CS   30144    // [bb][3][128]   3*384
#define OFF_EA   31296    // [bb][k*4+c]    3*512 (float4 per k)
#define OFF_X    32832    // h1: [bb*6477 + slot*51 + i] / G: [slot*101 + m]
#define H1BUF    6477
#define GSTR     101
#define OFF_UP   52264    // [kq*312 + c*104 + m]  (16B aligned; 312 & 104 are 16B multiples)
#define OFF_SIDX 53824
#define OFF_CNT  53952
#define OFF_ST   53956
#define SMEM_FLOATS 53964
#define SMEM_BYTES (SMEM_FLOATS * 4)

__device__ __forceinline__ float tanhx(float x) {
    float y; asm("tanh.approx.f32 %0, %1;" : "=f"(y) : "f"(x)); return y;
}
__device__ __forceinline__ u64 pack2(float lo, float hi) {
    u64 r; asm("mov.b64 %0, {%1, %2};" : "=l"(r) : "f"(lo), "f"(hi)); return r;
}
__device__ __forceinline__ float2 unpack2(u64 v) {
    float2 r; asm("mov.b64 {%0, %1}, %2;" : "=f"(r.x), "=f"(r.y) : "l"(v)); return r;
}
__device__ __forceinline__ u64 fma2(u64 a, u64 b, u64 c) {
    u64 r; asm("fma.rn.f32x2 %0, %1, %2, %3;" : "=l"(r) : "l"(a), "l"(b), "l"(c)); return r;
}
#define BARG(id) asm volatile("bar.sync %0, 128;" :: "r"(id) : "memory")

extern __shared__ float sm[];

template<int NB>
__device__ __forceinline__ void tile_body(
    const float* __restrict__ coords, float* __restrict__ out,
    int n, int tid, int qt, int slot, bool active, int j,
    const float* w0e, const float* b0e,
    const float* w1q, const float* b1q,
    const float* w2q, const float* b2q,
    int tbase1, int sz1, int barid, int b0i)
{
    __syncthreads();   // guard CS/EA/X reuse from previous tile
    for (int i = tid; i < NB * 384; i += THREADS) {
        int bb = i / 384, ii = i % 384;
        sm[OFF_CS + bb * 384 + (ii % 3) * 128 + ii / 3] =
            coords[(size_t)(b0i + bb) * 384 + ii];
    }
    __syncthreads();

    // ---- env: x[b] = 1/d, EA packed float4 (qt==0 writes) ----
    float x[NB];
    #pragma unroll
    for (int bb = 0; bb < NB; bb++) {
        const float* cs = sm + OFF_CS + bb * 384;
        float rx = cs[n]       - cs[j];
        float ry = cs[128 + n] - cs[128 + j];
        float rz = cs[256 + n] - cs[256 + j];
        float dinv = rsqrtf(rx * rx + ry * ry + rz * rz);
        float di2 = dinv * dinv;
        if (qt == 0 && active) {
            float4* ea4 = (float4*)(sm + OFF_EA + bb * 512);
            ea4[slot] = make_float4(rx * di2, ry * di2, rz * di2, 0.0f);
        }
        x[bb] = dinv;
    }

    // per-thread h1 row bases (hoisted once)
    const float* h1base[NB];
    #pragma unroll
    for (int bb = 0; bb < NB; bb++)
        h1base[bb] = sm + OFF_X + bb * H1BUF + slot * 51;

    // ---- layer1: quarter (13 real outs = 7 u64), h0 inline, NB batches ----
    {
        u64 acc[NB][7];
        {
            #pragma unroll
            for (int t = 0; t < 3; t++) {
                ulonglong2 bv = *(const ulonglong2*)(b1q + t * 4);
                #pragma unroll
                for (int bb = 0; bb < NB; bb++) { acc[bb][2*t] = bv.x; acc[bb][2*t+1] = bv.y; }
            }
            u64 bl = *(const u64*)(b1q + 12);
            #pragma unroll
            for (int bb = 0; bb < NB; bb++) acc[bb][6] = bl;
        }
        #pragma unroll
        for (int i = 0; i < 25; i++) {
            float w0 = w0e[i], bi0 = b0e[i];
            u64 hd[NB];
            #pragma unroll
            for (int bb = 0; bb < NB; bb++) {
                float h = tanhx(fmaf(x[bb], w0, bi0));
                hd[bb] = pack2(h, h);
            }
            const float* wp = w1q + i * 64;
            #pragma unroll
            for (int t = 0; t < 3; t++) {
                ulonglong2 w = *(const ulonglong2*)(wp + t * 4);
                #pragma unroll
                for (int bb = 0; bb < NB; bb++) {
                    acc[bb][2*t]   = fma2(w.x, hd[bb], acc[bb][2*t]);
                    acc[bb][2*t+1] = fma2(w.y, hd[bb], acc[bb][2*t+1]);
                }
            }
            u64 wl = *(const u64*)(wp + 12);
            #pragma unroll
            for (int bb = 0; bb < NB; bb++)
                acc[bb][6] = fma2(wl, hd[bb], acc[bb][6]);
        }
        if (active) {
            #pragma unroll
            for (int q = 0; q < 7; q++) {
                int l0 = 2 * q, l1 = 2 * q + 1;
                #pragma unroll
                for (int bb = 0; bb < NB; bb++) {
                    float2 v = unpack2(acc[bb][q]);
                    float* h1p = (float*)h1base[bb];
                    if (l0 < sz1) {
                        int o = tbase1 + l0, r = (o < 25) ? o : o - 25;
                        h1p[o] = tanhx(v.x) + tanhx(fmaf(x[bb], w0e[r], b0e[r]));
                    }
                    if (l1 < sz1) {
                        int o = tbase1 + l1, r = (o < 25) ? o : o - 25;
                        h1p[o] = tanhx(v.y) + tanhx(fmaf(x[bb], w0e[r], b0e[r]));
                    }
                }
            }
        }
    }
    BARG(barid);   // h1 complete within pair-group

    // ---- layer2: quarter 25 outs, two register sub-passes ----
    float g[NB][25];
    const int roff = 25 * (qt & 1);
    // sub-pass A: outs l in [0,16)
    {
        u64 acc[NB][8];
        #pragma unroll
        for (int t = 0; t < 4; t++) {
            ulonglong2 bv = *(const ulonglong2*)(b2q + t * 4);
            #pragma unroll
            for (int bb = 0; bb < NB; bb++) { acc[bb][2*t] = bv.x; acc[bb][2*t+1] = bv.y; }
        }
        #pragma unroll 2
        for (int c = 0; c < 10; c++) {
            float hr[NB][5];
            #pragma unroll
            for (int ii = 0; ii < 5; ii++)
                #pragma unroll
                for (int bb = 0; bb < NB; bb++)
                    hr[bb][ii] = h1base[bb][c * 5 + ii];
            #pragma unroll
            for (int ii = 0; ii < 5; ii++) {
                const float* wp = w2q + (c * 5 + ii) * 112;
                u64 hd[NB];
                #pragma unroll
                for (int bb = 0; bb < NB; bb++) hd[bb] = pack2(hr[bb][ii], hr[bb][ii]);
                #pragma unroll
                for (int t = 0; t < 4; t++) {
                    ulonglong2 w = *(const ulonglong2*)(wp + t * 4);
                    #pragma unroll
                    for (int bb = 0; bb < NB; bb++) {
                        acc[bb][2*t]   = fma2(w.x, hd[bb], acc[bb][2*t]);
                        acc[bb][2*t+1] = fma2(w.y, hd[bb], acc[bb][2*t+1]);
                    }
                }
            }
        }
        #pragma unroll
        for (int q = 0; q < 8; q++) {
            int l0 = 2 * q, l1 = 2 * q + 1;
            #pragma unroll
            for (int bb = 0; bb < NB; bb++) {
                float2 v = unpack2(acc[bb][q]);
                g[bb][l0] = tanhx(v.x) + h1base[bb][roff + l0];
                g[bb][l1] = tanhx(v.y) + h1base[bb][roff + l1];
            }
        }
    }
    // sub-pass B: outs l in [16,25): 5 u64 (last slot's hi is pad)
    {
        u64 acc[NB][5];
        {
            #pragma unroll
            for (int t = 0; t < 2; t++) {
                ulonglong2 bv = *(const ulonglong2*)(b2q + 16 + t * 4);
                #pragma unroll
                for (int bb = 0; bb < NB; bb++) { acc[bb][2*t] = bv.x; acc[bb][2*t+1] = bv.y; }
            }
            u64 bl = *(const u64*)(b2q + 24);
            #pragma unroll
            for (int bb = 0; bb < NB; bb++) acc[bb][4] = bl;
        }
        #pragma unroll 2
        for (int c = 0; c < 10; c++) {
            float hr[NB][5];
            #pragma unroll
            for (int ii = 0; ii < 5; ii++)
                #pragma unroll
                for (int bb = 0; bb < NB; bb++)
                    hr[bb][ii] = h1base[bb][c * 5 + ii];
            #pragma unroll
            for (int ii = 0; ii < 5; ii++) {
                const float* wp = w2q + (c * 5 + ii) * 112 + 16;
                u64 hd[NB];
                #pragma unroll
                for (int bb = 0; bb < NB; bb++) hd[bb] = pack2(hr[bb][ii], hr[bb][ii]);
                #pragma unroll
                for (int t = 0; t < 2; t++) {
                    ulonglong2 w = *(const ulonglong2*)(wp + t * 4);
                    #pragma unroll
                    for (int bb = 0; bb < NB; bb++) {
                        acc[bb][2*t]   = fma2(w.x, hd[bb], acc[bb][2*t]);
                        acc[bb][2*t+1] = fma2(w.y, hd[bb], acc[bb][2*t+1]);
                    }
                }
                u64 wl = *(const u64*)(wp + 8);
                #pragma unroll
                for (int bb = 0; bb < NB; bb++)
                    acc[bb][4] = fma2(wl, hd[bb], acc[bb][4]);
            }
        }
        #pragma unroll
        for (int q = 0; q < 5; q++) {
            int l0 = 16 + 2 * q, l1 = l0 + 1;
            #pragma unroll
            for (int bb = 0; bb < NB; bb++) {
                float2 v = unpack2(acc[bb][q]);
                if (l0 < 25) g[bb][l0] = tanhx(v.x) + h1base[bb][roff + l0];
                if (l1 < 25) g[bb][l1] = tanhx(v.y) + h1base[bb][roff + l1];
            }
        }
    }
    __syncthreads();   // all h1 reads done; X becomes G

    #pragma unroll
    for (int bb = 0; bb < NB; bb++) {
        // G store; safe to start right after previous batch's out (disjoint
        // regions: G=OFF_X vs UP; all UP reads of batch bb-1 happened before
        // the sync below in program order for every thread)
        if (active) {
            float* grow = sm + OFF_X + slot * GSTR + 25 * qt;
            #pragma unroll
            for (int l = 0; l < 25; l++) grow[l] = g[bb][l];
        }
        __syncthreads();   // G ready

        // U[c][m] = sum_k ea4[k]*G[k][m]; 4 k-chunks of 32 -> UP partials
        const int m  = tid & 127;
        const int kq = tid >> 7;
        if (m < 100) {
            float u0 = 0.0f, u1 = 0.0f, u2 = 0.0f;
            const int kb = kq * 32;
            const int ke = (kq == 3) ? KNB : kb + 32;
            const float* gp = sm + OFF_X + m;
            const float4* ep4 = (const float4*)(sm + OFF_EA + bb * 512);
            #pragma unroll 4
            for (int kk = kb; kk < ke; kk++) {
                float4 ea = ep4[kk];
                float gv = gp[kk * GSTR];
                u0 = fmaf(ea.x, gv, u0);
                u1 = fmaf(ea.y, gv, u1);
                u2 = fmaf(ea.z, gv, u2);
            }
            sm[OFF_UP + kq * 312 + m]       = u0;
            sm[OFF_UP + kq * 312 + 104 + m] = u1;
            sm[OFF_UP + kq * 312 + 208 + m] = u2;
        }
        __syncthreads();   // UP ready

        // fused reduce + out: own us from UP, a-vectors from UP cols 0..3
        if (tid < 100) {
            float us0 = 0.0f, us1 = 0.0f, us2 = 0.0f;
            float4 a0 = make_float4(0.f, 0.f, 0.f, 0.f), a1 = a0, a2 = a0;
            #pragma unroll
            for (int qq = 0; qq < 4; qq++) {
                const float* up = sm + OFF_UP + qq * 312;
                us0 += up[tid];
                us1 += up[104 + tid];
                us2 += up[208 + tid];
                float4 t0 = *(const float4*)(up);
                float4 t1 = *(const float4*)(up + 104);
                float4 t2 = *(const float4*)(up + 208);
                a0.x += t0.x; a0.y += t0.y; a0.z += t0.z; a0.w += t0.w;
                a1.x += t1.x; a1.y += t1.y; a1.z += t1.z; a1.w += t1.w;
                a2.x += t2.x; a2.y += t2.y; a2.z += t2.z; a2.w += t2.w;
            }
            float4 r;
            r.x = us0 * a0.x + us1 * a1.x + us2 * a2.x;
            r.y = us0 * a0.y + us1 * a1.y + us2 * a2.y;
            r.z = us0 * a0.z + us1 * a1.z + us2 * a2.z;
            r.w = us0 * a0.w + us1 * a1.w + us2 * a2.w;
            *(float4*)(out + ((size_t)(b0i + bb) * NATOM + n) * 400 + tid * 4) = r;
        }
        // no trailing sync: next G store writes OFF_X (disjoint from UP);
        // next UP write is after next __syncthreads which all threads
        // (including out threads) must reach after finishing out.
    }
}

__global__ void __launch_bounds__(THREADS, 1)
feat_kernel(const float* __restrict__ coords, const int* __restrict__ types,
            const float* __restrict__ W0g, const float* __restrict__ B0g,
            const float* __restrict__ W1g, const float* __restrict__ B1g,
            const float* __restrict__ W2g, const float* __restrict__ B2g,
            float* __restrict__ out)
{
    const int n    = blockIdx.x;
    const int tid  = threadIdx.x;
    const int warp = tid >> 5;
    const int lane = tid & 31;
    const int pw   = warp & 3;
    const int qt   = warp >> 2;
    int* smi = (int*)sm;

    const int eb = types[n] * 4;

    for (int i = OFF_W0 + tid; i < OFF_CS; i += THREADS) sm[i] = 0.0f;
    if (tid < 128) smi[OFF_TY + tid] = types[tid];
    __syncthreads();

    for (int i = tid; i < 100; i += THREADS) {
        int o = i % 25, e = i / 25;
        sm[OFF_W0 + e * 40 + o] = W0g[(eb + e) * 25 + o];
        sm[OFF_B0 + e * 40 + o] = B0g[(eb + e) * 25 + o];
    }
    for (int idx = tid; idx < 4 * 50 * 25; idx += THREADS) {
        int i = idx % 25, o = (idx / 25) % 50, e = idx / 1250;
        int pos = (o < 13) ? o : (o < 26) ? o + 3 : (o < 38) ? o + 6 : o + 10;
        sm[OFF_W1 + e * E1STR + i * 64 + pos] = W1g[(eb + e) * 1250 + o * 25 + i];
    }
    for (int idx = tid; idx < 200; idx += THREADS) {
        int o = idx % 50, e = idx / 50;
        int pos = (o < 13) ? o : (o < 26) ? o + 3 : (o < 38) ? o + 6 : o + 10;
        sm[OFF_B1 + e * 72 + pos] = B1g[(eb + e) * 50 + o];
    }
    for (int idx = tid; idx < 4 * 100 * 50; idx += THREADS) {
        int i = idx % 50, m = (idx / 50) % 100, e = idx / 5000;
        int pos = m + 3 * (m / 25);
        sm[OFF_W2 + e * E2STR + i * 112 + pos] = W2g[(eb + e) * 5000 + m * 50 + i];
    }
    for (int idx = tid; idx < 400; idx += THREADS) {
        int m = idx % 100, e = idx / 100;
        int pos = m + 3 * (m / 25);
        sm[OFF_B2 + e * 136 + pos] = B2g[(eb + e) * 100 + m];
    }

    if (tid < 4) {
        int c = 0;
        for (int j2 = 0; j2 < 128; j2++)
            if (j2 != n && smi[OFF_TY + j2] == tid) c++;
        smi[OFF_CNT + tid] = c;
    }
    __syncthreads();
    if (tid == 0) {
        int s = 0;
        #pragma unroll
        for (int e = 0; e < 4; e++) { smi[OFF_ST + e] = s; s += smi[OFF_CNT + e]; }
        smi[OFF_ST + 4] = s;
    }
    __syncthreads();
    if (tid < 128 && tid != n) {
        int t = smi[OFF_TY + tid];
        int r = 0;
        for (int j2 = 0; j2 < tid; j2++)
            if (j2 != n && smi[OFF_TY + j2] == t) r++;
        smi[OFF_SIDX + smi[OFF_ST + t] + r] = tid;
    }
    __syncthreads();

    const int  slot   = (pw << 5) + lane;
    const bool active = slot < KNB;
    const int  j = active ? smi[OFF_SIDX + slot] : n;
    const int  e = active ? smi[OFF_TY + j] : 0;

    const float* w0e = sm + OFF_W0 + e * 40;
    const float* b0e = sm + OFF_B0 + e * 40;
    const float* w1q = sm + OFF_W1 + e * E1STR + 16 * qt;
    const float* b1q = sm + OFF_B1 + e * 72 + 16 * qt;
    const float* w2q = sm + OFF_W2 + e * E2STR + 28 * qt;
    const float* b2q = sm + OFF_B2 + e * 136 + 28 * qt;
    const int sz1    = (qt < 2) ? 13 : 12;
    const int tbase1 = (qt < 2) ? 13 * qt : 12 * qt + 2;
    const int barid  = 1 + pw;
    const int bbase  = blockIdx.y * BT;

    tile_body<3>(coords, out, n, tid, qt, slot, active, j,
                 w0e, b0e, w1q, b1q, w2q, b2q, tbase1, sz1, barid, bbase);
    tile_body<3>(coords, out, n, tid, qt, slot, active, j,
                 w0e, b0e, w1q, b1q, w2q, b2q, tbase1, sz1, barid, bbase + 3);
    tile_body<2>(coords, out, n, tid, qt, slot, active, j,
                 w0e, b0e, w1q, b1q, w2q, b2q, tbase1, sz1, barid, bbase + 6);
}

extern "C" void kernel_launch(void* const* d_in, const int* in_sizes, int n_in,
                              void* d_out, int out_size)
{
    (void)in_sizes; (void)n_in; (void)out_size;
    const float* coords = (const float*)d_in[0];
    const int*   types  = (const int*)d_in[1];
    const float* W0g = (const float*)d_in[2];
    const float* B0g = (const float*)d_in[3];
    const float* W1g = (const float*)d_in[4];
    const float* B1g = (const float*)d_in[5];
    const float* W2g = (const float*)d_in[6];
    const float* B2g = (const float*)d_in[7];
    float* out = (float*)d_out;

    cudaFuncSetAttribute(feat_kernel, cudaFuncAttributeMaxDynamicSharedMemorySize, SMEM_BYTES);

    dim3 grid(NATOM, NBATCH / BT);   // (128, 8)
    feat_kernel<<<grid, THREADS, SMEM_BYTES>>>(coords, types,
                                               W0g, B0g, W1g, B1g, W2g, B2g, out);
}